// round 8
// baseline (speedup 1.0000x reference)
#include <cuda_runtime.h>
#include <cuda_bf16.h>

// Problem constants
#define Bc    16
#define Sc    1024
#define Dc    768
#define NSc   256
#define MAXWc 8
#define Vc    128
#define Cc    6
#define Rc    512
#define RELc  97
#define HIDc  384
#define DISc  20

// Packed f32x2 helpers (sm_103a FFMA2 path; ptxas never auto-fuses)
#define PACK2(d, lo, hi) \
    asm("mov.b64 %0, {%1, %2};" : "=l"(d) \
        : "r"(__float_as_uint(lo)), "r"(__float_as_uint(hi)))
#define FMA2(d, a, b) \
    asm("fma.rn.f32x2 %0, %1, %2, %0;" : "+l"(d) : "l"(a), "l"(b))
#define UNPACK2(lo, hi, s) \
    asm("mov.b64 {%0, %1}, %2;" : "=r"(lo), "=r"(hi) : "l"(s))

// Scratch (device globals -- no allocation allowed)
__device__ float g_span[Bc * NSc * Dc];      // span max-pool        12.6 MB
__device__ float g_ve[Bc * Vc * Dc];         // vertex embeddings     6.3 MB (L2-resident)
__device__ float g_HWh[Bc * Vc * HIDc];      // vertex @ W1[0:768]    3.0 MB
__device__ float g_HWt[Bc * Vc * HIDc];      // vertex @ W1[788:1556] 3.0 MB
__device__ float g_DTh[DISc * HIDc];         // dis @ W1[768:788]
__device__ float g_DTt[DISc * HIDc];         // dis @ W1[1556:1576]
__device__ float g_hidden[Bc * Rc * HIDc];   // relu(...)            12.6 MB

// ---------------------------------------------------------------------------
// 1) span max-pool  (192 threads = exactly Dc/4 float4 lanes)
// ---------------------------------------------------------------------------
__global__ void span_kernel(const float* __restrict__ repr,
                            const int* __restrict__ esi) {
    int blk = blockIdx.x;              // b*NS + s
    int b = blk >> 8;                  // NS = 256
    int start = esi[blk * 2 + 0];
    int end   = esi[blk * 2 + 1];
    int width = end - start;
    if (width > MAXWc - 1) width = MAXWc - 1;
    if (width < 0) width = 0;
    const float4* base = reinterpret_cast<const float4*>(
        repr + ((size_t)b * Sc + start) * Dc);
    float4* dst = reinterpret_cast<float4*>(g_span + (size_t)blk * Dc);
    int d = threadIdx.x;               // 0..191, Dc/4 == 192
    float4 mx = base[d];
    for (int w = 1; w <= width; ++w) {
        float4 t = base[(size_t)w * (Dc / 4) + d];
        mx.x = fmaxf(mx.x, t.x); mx.y = fmaxf(mx.y, t.y);
        mx.z = fmaxf(mx.z, t.z); mx.w = fmaxf(mx.w, t.w);
    }
    dst[d] = mx;
}

// ---------------------------------------------------------------------------
// 2) vertex masked mean
// ---------------------------------------------------------------------------
__global__ void vertex_kernel(const int* __restrict__ vidx,
                              const int* __restrict__ vmask) {
    int blk = blockIdx.x;              // b*V + v
    int b = blk >> 7;                  // V = 128
    int idx[Cc];
    float mk[Cc];
    float cnt = 0.f;
#pragma unroll
    for (int c = 0; c < Cc; ++c) {
        idx[c] = vidx[blk * Cc + c];
        mk[c] = (float)vmask[blk * Cc + c];
        cnt += mk[c];
    }
    float inv = 1.0f / fmaxf(cnt, 1.0f);
    const float4* sp = reinterpret_cast<const float4*>(g_span + (size_t)b * NSc * Dc);
    float4* dst = reinterpret_cast<float4*>(g_ve + (size_t)blk * Dc);
    int d = threadIdx.x;               // 192 == Dc/4
    float ax = 0.f, ay = 0.f, az = 0.f, aw = 0.f;
#pragma unroll
    for (int c = 0; c < Cc; ++c) {
        float4 t = sp[(size_t)idx[c] * (Dc / 4) + d];
        ax += mk[c] * t.x; ay += mk[c] * t.y;
        az += mk[c] * t.z; aw += mk[c] * t.w;
    }
    dst[d] = make_float4(ax * inv, ay * inv, az * inv, aw * inv);
}

// ---------------------------------------------------------------------------
// 3) distance tables
// ---------------------------------------------------------------------------
__global__ void dis_kernel(const float* __restrict__ dis_embed,
                           const float* __restrict__ W1) {
    int i = blockIdx.x;                // 20 blocks
    int h = threadIdx.x;               // 384 threads
    float ah = 0.f, at = 0.f;
#pragma unroll
    for (int k = 0; k < DISc; ++k) {
        float e = dis_embed[i * DISc + k];
        ah += e * W1[(size_t)(768 + k) * HIDc + h];
        at += e * W1[(size_t)(1556 + k) * HIDc + h];
    }
    g_DTh[i * HIDc + h] = ah;
    g_DTt[i * HIDc + h] = at;
}

// ---------------------------------------------------------------------------
// Packed inner product step. acc2[p][j]: rows (2p,2p+1) x col j as f32x2.
// B columns per thread: {tx*4+0..3} (j 0..3) and {64+tx*4+0..3} (j 4..7);
// the split-at-64 pattern makes B-tile LDS conflict-free (banks tx*4 mod 32).
// ---------------------------------------------------------------------------
__device__ __forceinline__ void fma2_step8(
    unsigned long long acc2[4][8],
    const float* __restrict__ As_row,   // &As[buf][k][ty*8]
    const float* __restrict__ Bs_krow,  // &Bs[buf][k][0]
    int tx)
{
    float4 a0 = *reinterpret_cast<const float4*>(As_row);
    float4 a1 = *reinterpret_cast<const float4*>(As_row + 4);
    float4 b0 = *reinterpret_cast<const float4*>(Bs_krow + tx * 4);
    float4 b1 = *reinterpret_cast<const float4*>(Bs_krow + 64 + tx * 4);
    unsigned long long pa[4], bb[8];
    PACK2(pa[0], a0.x, a0.y);
    PACK2(pa[1], a0.z, a0.w);
    PACK2(pa[2], a1.x, a1.y);
    PACK2(pa[3], a1.z, a1.w);
    PACK2(bb[0], b0.x, b0.x);
    PACK2(bb[1], b0.y, b0.y);
    PACK2(bb[2], b0.z, b0.z);
    PACK2(bb[3], b0.w, b0.w);
    PACK2(bb[4], b1.x, b1.x);
    PACK2(bb[5], b1.y, b1.y);
    PACK2(bb[6], b1.z, b1.z);
    PACK2(bb[7], b1.w, b1.w);
#pragma unroll
    for (int p = 0; p < 4; ++p)
#pragma unroll
        for (int j = 0; j < 8; ++j)
            FMA2(acc2[p][j], pa[p], bb[j]);
}

__device__ __forceinline__ void unpack_acc8(
    const unsigned long long acc2[4][8], float acc[8][8])
{
#pragma unroll
    for (int p = 0; p < 4; ++p)
#pragma unroll
        for (int j = 0; j < 8; ++j) {
            unsigned int lo, hi;
            UNPACK2(lo, hi, acc2[p][j]);
            acc[2 * p + 0][j] = __uint_as_float(lo);
            acc[2 * p + 1][j] = __uint_as_float(hi);
        }
}

// Column index for accumulator slot j (0..7) given tx: split-at-64 layout.
__device__ __forceinline__ int col_of(int tx, int j) {
    return (j < 4) ? (tx * 4 + j) : (64 + tx * 4 + (j - 4));
}

// ---------------------------------------------------------------------------
// fp32 SGEMM body, double-buffered, FFMA2: C = A@B (+bvec),
// 128x128x16 tile, 256 threads, 8x8 per thread, 1 barrier per k-step.
// Requires: M % 128 == 0, K % 16 == 0, lda % 4 == 0. N may be ragged.
// ---------------------------------------------------------------------------
__device__ __forceinline__ void sgemm_body(
    const float* __restrict__ A, int lda,
    const float* __restrict__ Bm, int ldb,
    const float* __restrict__ bvec,    // [N] or nullptr
    float* __restrict__ Cm, int ldc,
    int N, int K)
{
    __shared__ __align__(16) float As[2][16][132];
    __shared__ __align__(16) float Bs[2][16][128];

    int tid = threadIdx.x;
    int tx = tid & 15;                 // 8 cols each (split at 64)
    int ty = tid >> 4;                 // 8 rows each
    int m0 = blockIdx.y * 128;
    int n0 = blockIdx.x * 128;

    unsigned long long acc2[4][8] = {};   // bit pattern 0 == (0.f, 0.f)

    int ar  = tid >> 1;                // 0..127 A row
    int ac4 = tid & 1;                 // float4 col pair selector
    int bcn = tid & 127;               // B col 0..127
    int brb = tid >> 7;                // 0..1 base row
    bool bok = (n0 + bcn) < N;
    const float* bcol = Bm + (size_t)n0 + bcn;
    const float* arow = A + (size_t)(m0 + ar) * lda;

    // Preload k-step 0 into buffer 0
#pragma unroll
    for (int h = 0; h < 2; ++h) {
        int c4 = ac4 + h * 2;
        float4 a4 = reinterpret_cast<const float4*>(arow)[c4];
        As[0][c4 * 4 + 0][ar] = a4.x;
        As[0][c4 * 4 + 1][ar] = a4.y;
        As[0][c4 * 4 + 2][ar] = a4.z;
        As[0][c4 * 4 + 3][ar] = a4.w;
    }
#pragma unroll
    for (int i = 0; i < 8; ++i) {
        int kk = brb + i * 2;
        Bs[0][kk][bcn] = bok ? bcol[(size_t)kk * ldb] : 0.f;
    }
    __syncthreads();

    int NK = K / 16;
    for (int it = 0; it < NK; ++it) {
        int buf = it & 1;
        float4 pa[2];
        float bnx[8];
        bool has_next = (it + 1 < NK);
        if (has_next) {
            int k0 = (it + 1) * 16;
#pragma unroll
            for (int h = 0; h < 2; ++h) {
                int c4 = ac4 + h * 2;
                pa[h] = reinterpret_cast<const float4*>(arow + k0)[c4];
            }
#pragma unroll
            for (int i = 0; i < 8; ++i) {
                int kk = brb + i * 2;
                bnx[i] = bok ? bcol[(size_t)(k0 + kk) * ldb] : 0.f;
            }
        }
#pragma unroll
        for (int k = 0; k < 16; ++k)
            fma2_step8(acc2, &As[buf][k][ty * 8], &Bs[buf][k][0], tx);
        if (has_next) {
            int nb = buf ^ 1;
#pragma unroll
            for (int h = 0; h < 2; ++h) {
                int c4 = ac4 + h * 2;
                As[nb][c4 * 4 + 0][ar] = pa[h].x;
                As[nb][c4 * 4 + 1][ar] = pa[h].y;
                As[nb][c4 * 4 + 2][ar] = pa[h].z;
                As[nb][c4 * 4 + 3][ar] = pa[h].w;
            }
#pragma unroll
            for (int i = 0; i < 8; ++i)
                Bs[nb][brb + i * 2][bcn] = bnx[i];
            __syncthreads();
        }
    }

    float acc[8][8];
    unpack_acc8(acc2, acc);

#pragma unroll
    for (int i = 0; i < 8; ++i) {
        int m = m0 + ty * 8 + i;
#pragma unroll
        for (int j = 0; j < 8; ++j) {
            int n = n0 + col_of(tx, j);
            if (n < N) {
                float v = acc[i][j];
                if (bvec) v += bvec[n];
                Cm[(size_t)m * ldc + n] = v;
            }
        }
    }
}

// Combined vertex@W1 slices: blockIdx.z selects head (0) / tail (1) slice.
__global__ void __launch_bounds__(256, 1) gemm_vw(const float* __restrict__ W1) {
    if (blockIdx.z == 0)
        sgemm_body(g_ve, Dc, W1, HIDc, nullptr, g_HWh, HIDc, HIDc, Dc);
    else
        sgemm_body(g_ve, Dc, W1 + (size_t)788 * HIDc, HIDc, nullptr,
                   g_HWt, HIDc, HIDc, Dc);
}

__global__ void __launch_bounds__(256, 1) gemm_out(const float* __restrict__ W2,
                                                   const float* __restrict__ b2,
                                                   float* __restrict__ out) {
    sgemm_body(g_hidden, HIDc, W2, RELc, b2, out, RELc, RELc, HIDc);
}

// ---------------------------------------------------------------------------
// Fused main GEMM: hidden = relu( (ve[h]*ve[t]) @ W1p + HWh[h]+HWt[t]+DTh+DTt )
// A generated on the fly (g_ve L2-resident), bias gathered in epilogue.
// 128x128 tile, K=768, double-buffered smem, 1 barrier per k-step, FFMA2.
// ---------------------------------------------------------------------------
__global__ void __launch_bounds__(256, 1) gemm_main_fused(
    const float* __restrict__ W1,
    const int* __restrict__ hti,
    const int* __restrict__ dh,
    const int* __restrict__ dt)
{
    __shared__ __align__(16) float As[2][16][132];
    __shared__ __align__(16) float Bs[2][16][128];
    __shared__ int sh_h[128], sh_t[128], sh_dh[128], sh_dt[128];

    const float* Bm = W1 + (size_t)1576 * HIDc;   // product-term slice of W1
    int tid = threadIdx.x;
    int m0 = blockIdx.y * 128;
    int n0 = blockIdx.x * 128;

    if (tid < 128) {
        int m = m0 + tid;
        sh_h[tid]  = hti[m * 2 + 0];
        sh_t[tid]  = hti[m * 2 + 1];
        sh_dh[tid] = dh[m];
        sh_dt[tid] = dt[m];
    }

    // A-loader mapping
    int ar  = tid >> 1;
    int ac4 = tid & 1;
    // B-loader mapping
    int bcn = tid & 127;
    int brb = tid >> 7;
    const float* bcol = Bm + (size_t)n0 + bcn;

    int m_a = m0 + ar;
    int b_a = m_a >> 9;                // R = 512
    int hia = hti[m_a * 2 + 0];
    int tia = hti[m_a * 2 + 1];
    const float4* vh = reinterpret_cast<const float4*>(
        g_ve + ((size_t)b_a * Vc + hia) * Dc);
    const float4* vt = reinterpret_cast<const float4*>(
        g_ve + ((size_t)b_a * Vc + tia) * Dc);

    int tx = tid & 15;
    int ty = tid >> 4;
    unsigned long long acc2[4][8] = {};

    // Preload tile 0 into buffer 0
#pragma unroll
    for (int h = 0; h < 2; ++h) {
        int c4 = ac4 + h * 2;
        float4 a = vh[c4];
        float4 c = vt[c4];
        As[0][c4 * 4 + 0][ar] = a.x * c.x;
        As[0][c4 * 4 + 1][ar] = a.y * c.y;
        As[0][c4 * 4 + 2][ar] = a.z * c.z;
        As[0][c4 * 4 + 3][ar] = a.w * c.w;
    }
#pragma unroll
    for (int i = 0; i < 8; ++i) {
        int kk = brb + i * 2;
        Bs[0][kk][bcn] = bcol[(size_t)kk * HIDc];
    }
    __syncthreads();

    const int NK = Dc / 16;            // 48 k-steps
    for (int it = 0; it < NK; ++it) {
        int buf = it & 1;
        float4 pa[2];
        float bnx[8];
        bool has_next = (it + 1 < NK);
        if (has_next) {
            int kb = (it + 1) * 4;     // float4 base index into ve row
#pragma unroll
            for (int h = 0; h < 2; ++h) {
                int c4 = ac4 + h * 2;
                float4 a = vh[kb + c4];
                float4 c = vt[kb + c4];
                pa[h] = make_float4(a.x * c.x, a.y * c.y, a.z * c.z, a.w * c.w);
            }
            int k0 = (it + 1) * 16;
#pragma unroll
            for (int i = 0; i < 8; ++i) {
                int kk = brb + i * 2;
                bnx[i] = bcol[(size_t)(k0 + kk) * HIDc];
            }
        }
#pragma unroll
        for (int k = 0; k < 16; ++k)
            fma2_step8(acc2, &As[buf][k][ty * 8], &Bs[buf][k][0], tx);
        if (has_next) {
            int nb = buf ^ 1;
#pragma unroll
            for (int h = 0; h < 2; ++h) {
                int c4 = ac4 + h * 2;
                As[nb][c4 * 4 + 0][ar] = pa[h].x;
                As[nb][c4 * 4 + 1][ar] = pa[h].y;
                As[nb][c4 * 4 + 2][ar] = pa[h].z;
                As[nb][c4 * 4 + 3][ar] = pa[h].w;
            }
#pragma unroll
            for (int i = 0; i < 8; ++i)
                Bs[nb][brb + i * 2][bcn] = bnx[i];
            __syncthreads();
        }
    }

    float acc[8][8];
    unpack_acc8(acc2, acc);

    // Epilogue: gathered 4-way bias + relu. Columns split at 64 per thread;
    // N=384 exact (n0<=256, max n = n0+64+60+3 = 383), no guard needed.
#pragma unroll
    for (int i = 0; i < 8; ++i) {
        int lr = ty * 8 + i;
        int m = m0 + lr;
        int b = m >> 9;
        const float* bh = g_HWh + ((size_t)b * Vc + sh_h[lr]) * HIDc;
        const float* bt = g_HWt + ((size_t)b * Vc + sh_t[lr]) * HIDc;
        const float* th = g_DTh + (size_t)sh_dh[lr] * HIDc;
        const float* tt = g_DTt + (size_t)sh_dt[lr] * HIDc;
#pragma unroll
        for (int half = 0; half < 2; ++half) {
            int n = n0 + half * 64 + tx * 4;
            float4 f1 = *reinterpret_cast<const float4*>(bh + n);
            float4 f2 = *reinterpret_cast<const float4*>(bt + n);
            float4 f3 = *reinterpret_cast<const float4*>(th + n);
            float4 f4 = *reinterpret_cast<const float4*>(tt + n);
            int j = half * 4;
            float4 v;
            v.x = fmaxf(acc[i][j + 0] + f1.x + f2.x + f3.x + f4.x, 0.f);
            v.y = fmaxf(acc[i][j + 1] + f1.y + f2.y + f3.y + f4.y, 0.f);
            v.z = fmaxf(acc[i][j + 2] + f1.z + f2.z + f3.z + f4.z, 0.f);
            v.w = fmaxf(acc[i][j + 3] + f1.w + f2.w + f3.w + f4.w, 0.f);
            *reinterpret_cast<float4*>(g_hidden + (size_t)m * HIDc + n) = v;
        }
    }
}

// ---------------------------------------------------------------------------
extern "C" void kernel_launch(void* const* d_in, const int* in_sizes, int n_in,
                              void* d_out, int out_size) {
    const float* repr      = (const float*)d_in[0];   // sentence_repr
    const int*   esi       = (const int*)  d_in[1];   // entity_span_indices
    // d_in[2] entity_span_indices_mask: unused by reference
    const int*   vidx      = (const int*)  d_in[3];   // vertex_indices
    const int*   vmask     = (const int*)  d_in[4];   // vertex_indices_mask
    const int*   hti       = (const int*)  d_in[5];   // head_tail_indices
    // d_in[6] relation_mask: unused by reference
    const int*   dht       = (const int*)  d_in[7];   // dis_h_2_t
    const int*   dth       = (const int*)  d_in[8];   // dis_t_2_h
    const float* dis_embed = (const float*)d_in[9];
    const float* W1        = (const float*)d_in[10];
    const float* W2        = (const float*)d_in[11];
    const float* b2        = (const float*)d_in[12];
    float* out = (float*)d_out;

    span_kernel<<<Bc * NSc, 192>>>(repr, esi);
    vertex_kernel<<<Bc * Vc, 192>>>(vidx, vmask);
    dis_kernel<<<DISc, HIDc>>>(dis_embed, W1);

    dim3 g1(HIDc / 128, (Bc * Vc) / 128, 2);   // (3, 16, 2)
    gemm_vw<<<g1, 256>>>(W1);

    dim3 g2(HIDc / 128, (Bc * Rc) / 128);      // (3, 64)
    gemm_main_fused<<<g2, 256>>>(W1, hti, dht, dth);

    dim3 g3((RELc + 127) / 128, (Bc * Rc) / 128);  // (1, 64)
    gemm_out<<<g3, 256>>>(W2, b2, out);
}